// round 7
// baseline (speedup 1.0000x reference)
#include <cuda_runtime.h>
#include <cuda_bf16.h>
#include <cstdint>

// DifferentiableTopKSelector == per-row hard top-32 mask of raw scores
// (straight-through estimator is value-identical to hard_mask; `u` is dead).
//
// Round 7: persistent CTAs + 3-buffer TMA ring. Single-shot TMA (R5) was
// neutral because each CTA serialized load-latency -> compute -> store.
// Now each CTA streams ~14 rows: TMA load of row j+1 overlaps compute on
// row j overlaps TMA store of row j-1's mask. Both 128 MB streams bypass
// L1tex; compute (guess-threshold candidate gather + exact stable rank on
// ~88 composite keys) hides entirely under the DMA stream.

static constexpr int COLS = 8192;
static constexpr int NT   = 256;
static constexpr int VPT  = COLS / 4 / NT;   // 8 float4 per thread
static constexpr int CAP  = 256;
static constexpr int KSEL = 32;
static constexpr int NBUF = 3;
static constexpr unsigned ROW_BYTES = COLS * 4;   // 32 KB
static constexpr int GRID = 296;                  // 2 CTAs/SM * 148 SMs
#define GUESS 2.3f

__device__ __forceinline__ uint32_t smem_u32(const void* p) {
    uint32_t a;
    asm("{ .reg .u64 t; cvta.to.shared.u64 t, %1; cvt.u32.u64 %0, t; }"
        : "=r"(a) : "l"(p));
    return a;
}

__device__ __forceinline__ unsigned long long pack_key(float v, unsigned idx) {
    // v > GUESS > 0: float bits compare as unsigned. Inverted index makes
    // larger composite == (larger value, then smaller index) — exactly
    // jax.lax.top_k's stable tie-break.
    return ((unsigned long long)__float_as_uint(v) << 32)
         | (unsigned long long)(COLS - 1u - idx);
}

__global__ void __launch_bounds__(NT)
topk_mask_kernel(const float* __restrict__ scores, float* __restrict__ out,
                 int rows) {
    extern __shared__ __align__(128) float buf[];        // NBUF * 32 KB ring
    __shared__ unsigned long long  cand[CAP];            // 2 KB
    __shared__ unsigned            w[KSEL];
    __shared__ int                 s_cnt;
    __shared__ __align__(8) unsigned long long mbar[NBUF];

    const int t = threadIdx.x;
    if (t == 0) {
        s_cnt = 0;
        #pragma unroll
        for (int i = 0; i < NBUF; ++i)
            asm volatile("mbarrier.init.shared.b64 [%0], 1;"
                         :: "r"(smem_u32(&mbar[i])) : "memory");
    }
    __syncthreads();

    const int stride = gridDim.x;
    const int r0 = blockIdx.x;
    unsigned phbits = 0;    // expected parity bit per buffer

    // ---- prologue: kick off load of this CTA's first row into buffer 0 ----
    if (t == 0 && r0 < rows) {
        const uint32_t mb = smem_u32(&mbar[0]);
        asm volatile("mbarrier.arrive.expect_tx.shared.b64 _, [%0], %1;"
                     :: "r"(mb), "r"(ROW_BYTES) : "memory");
        asm volatile(
            "cp.async.bulk.shared::cta.global.mbarrier::complete_tx::bytes "
            "[%0], [%1], %2, [%3];"
            :: "r"(smem_u32(buf)), "l"(scores + (size_t)r0 * COLS),
               "r"(ROW_BYTES), "r"(mb) : "memory");
    }

    int b = 0;
    for (int r = r0; r < rows; r += stride) {
        const int rn = r + stride;
        const int bn = (b + 1 == NBUF) ? 0 : b + 1;

        // ---- prefetch next row into buffer bn (store from 2 iters ago is
        //      guaranteed drained by wait_group 1) ----
        if (t == 0 && rn < rows) {
            asm volatile("cp.async.bulk.wait_group 1;" ::: "memory");
            const uint32_t mb = smem_u32(&mbar[bn]);
            asm volatile("mbarrier.arrive.expect_tx.shared.b64 _, [%0], %1;"
                         :: "r"(mb), "r"(ROW_BYTES) : "memory");
            asm volatile(
                "cp.async.bulk.shared::cta.global.mbarrier::complete_tx::bytes "
                "[%0], [%1], %2, [%3];"
                :: "r"(smem_u32(buf + (size_t)bn * COLS)),
                   "l"(scores + (size_t)rn * COLS),
                   "r"(ROW_BYTES), "r"(mb) : "memory");
        }

        // ---- wait for current row's data (fast path: issued 1 iter ago) ----
        {
            const uint32_t mb = smem_u32(&mbar[b]);
            const unsigned par = (phbits >> b) & 1u;
            asm volatile(
                "{\n\t.reg .pred P;\n"
                "W%=:\n\t"
                "mbarrier.try_wait.parity.acquire.cta.shared::cta.b64 P, [%0], %1, 0x989680;\n\t"
                "@!P bra W%=;\n\t}"
                :: "r"(mb), "r"(par) : "memory");
            phbits ^= 1u << b;
        }

        float* cur = buf + (size_t)b * COLS;
        const float4* c4 = (const float4*)cur;

        // ---- candidate detection (conflict-free LDS.128) ----
        #pragma unroll
        for (int it = 0; it < VPT; ++it) {
            float4 v = c4[t + it * NT];
            if (fmaxf(fmaxf(v.x, v.y), fmaxf(v.z, v.w)) > GUESS) {
                unsigned long long loc[4];
                int n = 0;
                const unsigned base = (unsigned)((t + it * NT) * 4);
                if (v.x > GUESS) loc[n++] = pack_key(v.x, base + 0u);
                if (v.y > GUESS) loc[n++] = pack_key(v.y, base + 1u);
                if (v.z > GUESS) loc[n++] = pack_key(v.z, base + 2u);
                if (v.w > GUESS) loc[n++] = pack_key(v.w, base + 3u);
                int slot = atomicAdd(&s_cnt, n);
                for (int q = 0; q < n; ++q)
                    if (slot + q < CAP) cand[slot + q] = loc[q];
            }
        }
        __syncthreads();
        const int cnt = s_cnt;

        if (cnt >= KSEL && cnt <= CAP) {
            // ---- exact stable rank; ranks unique -> direct slot write ----
            if (t < cnt) {
                const unsigned long long ci = cand[t];
                int rk = 0;
                #pragma unroll 4
                for (int j = 0; j < cnt; ++j)
                    rk += (cand[j] > ci);            // LDS.64 broadcast
                if (rk < KSEL)
                    w[rk] = COLS - 1u - (unsigned)(ci & 0xFFFFFFFFull);
            }
        } else if (t == 0) {
            // ---- exact serial fallback over smem copy (guard only) ----
            float    bk[KSEL];
            unsigned bi[KSEL];
            #pragma unroll
            for (int i = 0; i < KSEL; ++i) { bk[i] = -INFINITY; bi[i] = 0u; }
            for (int i = 0; i < COLS; ++i) {
                float vv = cur[i];
                if (vv > bk[KSEL - 1]) {             // strict > == stable
                    int p = KSEL - 1;
                    while (p > 0 && vv > bk[p - 1]) {
                        bk[p] = bk[p - 1]; bi[p] = bi[p - 1]; --p;
                    }
                    bk[p] = vv; bi[p] = (unsigned)i;
                }
            }
            for (int i = 0; i < KSEL; ++i) w[i] = bi[i];
        }
        __syncthreads();

        // ---- build mask in place: zero row, reset counter ----
        float4* cw = (float4*)cur;
        const float4 z = make_float4(0.f, 0.f, 0.f, 0.f);
        #pragma unroll
        for (int it = 0; it < VPT; ++it)
            cw[t + it * NT] = z;
        if (t == 0) s_cnt = 0;
        __syncthreads();
        if (t < KSEL) cur[w[t]] = 1.0f;
        __syncthreads();

        // ---- async bulk store of the mask; fire and forget ----
        asm volatile("fence.proxy.async.shared::cta;" ::: "memory");
        if (t == 0) {
            asm volatile(
                "cp.async.bulk.global.shared::cta.bulk_group [%0], [%1], %2;"
                :: "l"(out + (size_t)r * COLS), "r"(smem_u32(cur)),
                   "r"(ROW_BYTES) : "memory");
            asm volatile("cp.async.bulk.commit_group;" ::: "memory");
        }
        b = bn;
    }

    // drain outstanding stores before CTA exit
    if (t == 0)
        asm volatile("cp.async.bulk.wait_group 0;" ::: "memory");
}

extern "C" void kernel_launch(void* const* d_in, const int* in_sizes, int n_in,
                              void* d_out, int out_size) {
    const float* scores = (const float*)d_in[0];   // (4096, 8192) fp32
    // d_in[1] (u) is mathematically dead: output == hard top-k mask of scores.
    float* out = (float*)d_out;
    const int rows = out_size / COLS;              // 4096

    static bool attr_set = false;
    if (!attr_set) {
        cudaFuncSetAttribute(topk_mask_kernel,
                             cudaFuncAttributeMaxDynamicSharedMemorySize,
                             NBUF * (int)ROW_BYTES);
        attr_set = true;
    }
    const int grid = (rows < GRID) ? rows : GRID;
    topk_mask_kernel<<<grid, NT, NBUF * ROW_BYTES>>>(scores, out, rows);
}